// round 8
// baseline (speedup 1.0000x reference)
#include <cuda_runtime.h>
#include <math.h>

// ---------------------------------------------------------------------------
// MultiScaleAdaptiveElasticityLossWithLame
//   d_in[0]: deformation_field (2,3,160,192,160) f32
//   d_in[1]: image             (2,1,160,192,160) f32
//   out: scalar f32 loss
// ---------------------------------------------------------------------------

#define D0 160
#define H0 192
#define W0 160
#define D1 80
#define H1 96
#define W1 80
#define D2 40
#define H2 48
#define W2 40

#define VOL0 (D0*H0*W0)
#define VOL1 (D1*H1*W1)
#define VOL2 (D2*H2*W2)

__device__ float g_def1[2*3*VOL1];
__device__ float g_img1[2*1*VOL1];
__device__ float g_def2[2*3*VOL2];
__device__ float g_img2[2*1*VOL2];
__device__ double g_acc[3];

__global__ void init_acc_kernel() {
    if (threadIdx.x < 3) g_acc[threadIdx.x] = 0.0;
}

// ---------------------------------------------------------------------------
// Fused trilinear downsample (align_corners=True): def (6 planes) + img (2).
// One output per thread; all index decomposition from grid/block dims.
template<int Di, int Hi, int Wi, int Do, int Ho, int Wo>
__global__ void downsample_both(const float* __restrict__ def,
                                const float* __restrict__ img,
                                float* __restrict__ odef,
                                float* __restrict__ oimg,
                                float rD, float rH, float rW)
{
    constexpr int OVOL = Do * Ho * Wo;
    constexpr int IVOL = Di * Hi * Wi;

    int x = threadIdx.x;
    int y = blockIdx.x * blockDim.y + threadIdx.y;
    int z = blockIdx.y;
    int p = blockIdx.z;            // 0..7

    const float* in; float* outp;
    if (p < 6) { in = def + p * IVOL;       outp = odef + p * OVOL; }
    else       { in = img + (p - 6) * IVOL; outp = oimg + (p - 6) * OVOL; }

    float cz = (float)z * rD;
    float cy = (float)y * rH;
    float cx = (float)x * rW;
    int z0 = min((int)floorf(cz), Di - 1);
    int y0 = min((int)floorf(cy), Hi - 1);
    int x0 = min((int)floorf(cx), Wi - 1);
    float wz = cz - (float)z0;
    float wy = cy - (float)y0;
    float wx = cx - (float)x0;
    int z1 = min(z0 + 1, Di - 1);
    int y1 = min(y0 + 1, Hi - 1);
    int x1 = min(x0 + 1, Wi - 1);

    const float* pz0 = in + z0 * (Hi * Wi);
    const float* pz1 = in + z1 * (Hi * Wi);
    int oy0 = y0 * Wi, oy1 = y1 * Wi;

    float v000 = __ldg(pz0 + oy0 + x0), v001 = __ldg(pz0 + oy0 + x1);
    float v010 = __ldg(pz0 + oy1 + x0), v011 = __ldg(pz0 + oy1 + x1);
    float v100 = __ldg(pz1 + oy0 + x0), v101 = __ldg(pz1 + oy0 + x1);
    float v110 = __ldg(pz1 + oy1 + x0), v111 = __ldg(pz1 + oy1 + x1);

    float a00 = v000 * (1.f - wx) + v001 * wx;
    float a01 = v010 * (1.f - wx) + v011 * wx;
    float a10 = v100 * (1.f - wx) + v101 * wx;
    float a11 = v110 * (1.f - wx) + v111 * wx;
    float b0 = a00 * (1.f - wy) + a01 * wy;
    float b1 = a10 * (1.f - wy) + a11 * wy;
    outp[z * (Ho * Wo) + y * Wo + x] = b0 * (1.f - wz) + b1 * wz;
}

// ---------------------------------------------------------------------------
// torch.gradient of one field at 4 consecutive W positions.
template<int D, int H, int W>
__device__ __forceinline__ void field_grads(const float* __restrict__ f,
                                            int d, int h, int w,
                                            float4& gD, float4& gH, float4& gW_)
{
    constexpr int sH = W;
    constexpr int sD = H * W;
    const float* base = f + d * sD + h * sH + w;

    float4 c = __ldg(reinterpret_cast<const float4*>(base));

    float xl = (w > 0)     ? __ldg(base - 1) : 0.f;
    float xr = (w + 4 < W) ? __ldg(base + 4) : 0.f;
    gW_.x = (w == 0)     ? (c.y - c.x) : 0.5f * (c.y - xl);
    gW_.y = 0.5f * (c.z - c.x);
    gW_.z = 0.5f * (c.w - c.y);
    gW_.w = (w + 4 == W) ? (c.w - c.z) : 0.5f * (xr - c.z);

    float4 hm = __ldg(reinterpret_cast<const float4*>(base - (h > 0     ? sH : 0)));
    float4 hp = __ldg(reinterpret_cast<const float4*>(base + (h < H - 1 ? sH : 0)));
    float sh = (h == 0 || h == H - 1) ? 1.0f : 0.5f;
    gH.x = sh * (hp.x - hm.x); gH.y = sh * (hp.y - hm.y);
    gH.z = sh * (hp.z - hm.z); gH.w = sh * (hp.w - hm.w);

    float4 dm = __ldg(reinterpret_cast<const float4*>(base - (d > 0     ? sD : 0)));
    float4 dp = __ldg(reinterpret_cast<const float4*>(base + (d < D - 1 ? sD : 0)));
    float sd = (d == 0 || d == D - 1) ? 1.0f : 0.5f;
    gD.x = sd * (dp.x - dm.x); gD.y = sd * (dp.y - dm.y);
    gD.z = sd * (dp.z - dm.z); gD.w = sd * (dp.w - dm.w);
}

__device__ __forceinline__ float4 f4add(float4 a, float4 b) {
    return make_float4(a.x + b.x, a.y + b.y, a.z + b.z, a.w + b.w);
}

// ---------------------------------------------------------------------------
// Energy kernel with 3D thread blocks (4,8,8) = (xq, h, d): each block covers
// a 16W x 8H x 8D brick, so h/d neighbor loads are same-block centers -> L1.
template<int D, int H, int W>
__global__ void __launch_bounds__(256)
energy_brick(const float* __restrict__ def, const float* __restrict__ img,
             int scale_idx)
{
    constexpr int Wq = W >> 2;
    constexpr int VOL = D * H * W;
    constexpr int ZB = D / 8;            // d-blocks per batch

    int xq = blockIdx.x * 4 + threadIdx.x;
    int h  = blockIdx.y * 8 + threadIdx.y;
    int n  = blockIdx.z / ZB;
    int d  = (blockIdx.z % ZB) * 8 + threadIdx.z;

    float local = 0.f;
    if (xq < Wq) {
        int w = xq << 2;
        const float* base = def + n * 3 * VOL;

        float4 Exx, Eyy, Ezz, Sxy, Sxz, Syz;   // Sab = 2*Eab
        {
            float4 gD, gH, gW;
            field_grads<D, H, W>(base, d, h, w, gD, gH, gW);   // u
            Exx = gD; Sxy = gH; Sxz = gW;
        }
        {
            float4 gD, gH, gW;
            field_grads<D, H, W>(base + VOL, d, h, w, gD, gH, gW);   // v
            Eyy = gH; Sxy = f4add(Sxy, gD); Syz = gW;
        }
        {
            float4 gD, gH, gW;
            field_grads<D, H, W>(base + 2 * VOL, d, h, w, gD, gH, gW);   // w
            Ezz = gW; Sxz = f4add(Sxz, gD); Syz = f4add(Syz, gH);
        }
        float4 g2;
        {
            float4 gD, gH, gW;
            field_grads<D, H, W>(img + n * VOL, d, h, w, gD, gH, gW);
            g2.x = gD.x * gD.x + gH.x * gH.x + gW.x * gW.x;
            g2.y = gD.y * gD.y + gH.y * gH.y + gW.y * gW.y;
            g2.z = gD.z * gD.z + gH.z * gH.z + gW.z * gW.z;
            g2.w = gD.w * gD.w + gH.w * gH.w + gW.w * gW.w;
        }

        const float* exx = reinterpret_cast<const float*>(&Exx);
        const float* eyy = reinterpret_cast<const float*>(&Eyy);
        const float* ezz = reinterpret_cast<const float*>(&Ezz);
        const float* sxy = reinterpret_cast<const float*>(&Sxy);
        const float* sxz = reinterpret_cast<const float*>(&Sxz);
        const float* syz = reinterpret_cast<const float*>(&Syz);
        const float* gg  = reinterpret_cast<const float*>(&g2);

        #pragma unroll
        for (int j = 0; j < 4; j++) {
            float exy = 0.5f * sxy[j];
            float exz = 0.5f * sxz[j];
            float eyz = 0.5f * syz[j];
            float tr = exx[j] + eyy[j] + ezz[j];
            float g = sqrtf(gg[j]);
            float lam = 1.0f + 0.5f * g;
            float mu  = 1.0f + 0.5f * g;
            float e = 0.5f * lam * tr * tr
                    + mu * (exx[j] * exx[j] + eyy[j] * eyy[j] + ezz[j] * ezz[j]
                            + 2.0f * (exy * exy + exz * exz + eyz * eyz));
            local += (1.0f + 0.1f * g) * e;
        }
    }

    #pragma unroll
    for (int o = 16; o > 0; o >>= 1)
        local += __shfl_down_sync(0xffffffffu, local, o);

    __shared__ float ws[8];
    int tid  = threadIdx.x + threadIdx.y * 4 + threadIdx.z * 32;
    int lane = tid & 31;
    int wid  = tid >> 5;
    if (lane == 0) ws[wid] = local;
    __syncthreads();
    if (wid == 0) {
        float s = (lane < 8) ? ws[lane] : 0.f;
        #pragma unroll
        for (int o = 4; o > 0; o >>= 1)
            s += __shfl_down_sync(0xffffffffu, s, o);
        if (lane == 0)
            atomicAdd(&g_acc[scale_idx], (double)s);
    }
}

// ---------------------------------------------------------------------------
__global__ void finalize_kernel(float* out) {
    double m0 = g_acc[0] / (2.0 * VOL0);
    double m1 = g_acc[1] / (2.0 * VOL1);
    double m2 = g_acc[2] / (2.0 * VOL2);
    out[0] = (float)(m0 + m1 + m2);
}

// ---------------------------------------------------------------------------
extern "C" void kernel_launch(void* const* d_in, const int* in_sizes, int n_in,
                              void* d_out, int out_size)
{
    const float* def = (const float*)d_in[0];
    const float* img = (const float*)d_in[1];
    float* out = (float*)d_out;

    float *p_def1, *p_img1, *p_def2, *p_img2;
    cudaGetSymbolAddress((void**)&p_def1, g_def1);
    cudaGetSymbolAddress((void**)&p_img1, g_img1);
    cudaGetSymbolAddress((void**)&p_def2, g_def2);
    cudaGetSymbolAddress((void**)&p_img2, g_img2);

    // Lazily-created side stream + events (first call is the uncaptured
    // correctness run; captured replays reuse them).
    static cudaStream_t s_side = nullptr;
    static cudaEvent_t  s_fork = nullptr, s_join = nullptr;
    if (s_side == nullptr) {
        cudaStreamCreateWithFlags(&s_side, cudaStreamNonBlocking);
        cudaEventCreateWithFlags(&s_fork, cudaEventDisableTiming);
        cudaEventCreateWithFlags(&s_join, cudaEventDisableTiming);
    }

    init_acc_kernel<<<1, 32>>>();

    // Fork: side stream handles scales 1 & 2 concurrently with scale 0.
    cudaEventRecord(s_fork, 0);
    cudaStreamWaitEvent(s_side, s_fork, 0);

    const dim3 eblk(4, 8, 8);

    // ---- side stream: scale 1 then scale 2 ----
    {
        float rD = (float)((double)(D0 - 1) / (double)(D1 - 1));
        float rH = (float)((double)(H0 - 1) / (double)(H1 - 1));
        float rW = (float)((double)(W0 - 1) / (double)(W1 - 1));
        dim3 blk(W1, 3);
        dim3 grd(H1 / 3, D1, 8);
        downsample_both<D0, H0, W0, D1, H1, W1>
            <<<grd, blk, 0, s_side>>>(def, img, p_def1, p_img1, rD, rH, rW);

        dim3 eg1((W1 / 4 + 3) / 4, H1 / 8, 2 * (D1 / 8));
        energy_brick<D1, H1, W1><<<eg1, eblk, 0, s_side>>>(p_def1, p_img1, 1);
    }
    {
        float rD = (float)((double)(D0 - 1) / (double)(D2 - 1));
        float rH = (float)((double)(H0 - 1) / (double)(H2 - 1));
        float rW = (float)((double)(W0 - 1) / (double)(W2 - 1));
        dim3 blk(W2, 6);
        dim3 grd(H2 / 6, D2, 8);
        downsample_both<D0, H0, W0, D2, H2, W2>
            <<<grd, blk, 0, s_side>>>(def, img, p_def2, p_img2, rD, rH, rW);

        dim3 eg2((W2 / 4 + 3) / 4, H2 / 8, 2 * (D2 / 8));
        energy_brick<D2, H2, W2><<<eg2, eblk, 0, s_side>>>(p_def2, p_img2, 2);
    }

    // ---- main stream: scale 0 ----
    {
        dim3 eg0((W0 / 4 + 3) / 4, H0 / 8, 2 * (D0 / 8));
        energy_brick<D0, H0, W0><<<eg0, eblk>>>(def, img, 0);
    }

    // Join, then finalize.
    cudaEventRecord(s_join, s_side);
    cudaStreamWaitEvent(0, s_join, 0);
    finalize_kernel<<<1, 1>>>(out);
}

// round 9
// speedup vs baseline: 1.2403x; 1.2403x over previous
#include <cuda_runtime.h>
#include <math.h>

// ---------------------------------------------------------------------------
// MultiScaleAdaptiveElasticityLossWithLame
//   d_in[0]: deformation_field (2,3,160,192,160) f32
//   d_in[1]: image             (2,1,160,192,160) f32
//   out: scalar f32 loss
// ---------------------------------------------------------------------------

#define D0 160
#define H0 192
#define W0 160
#define D1 80
#define H1 96
#define W1 80
#define D2 40
#define H2 48
#define W2 40

#define VOL0 (D0*H0*W0)
#define VOL1 (D1*H1*W1)
#define VOL2 (D2*H2*W2)

__device__ float g_def1[2*3*VOL1];
__device__ float g_img1[2*1*VOL1];
__device__ float g_def2[2*3*VOL2];
__device__ float g_img2[2*1*VOL2];
__device__ double g_acc[3];

__global__ void init_acc_kernel() {
    if (threadIdx.x < 3) g_acc[threadIdx.x] = 0.0;
}

// ---------------------------------------------------------------------------
// Fused trilinear downsample (align_corners=True): def (6 planes) + img (2).
// One output per thread; all index decomposition from grid/block dims:
//   x = threadIdx.x, y = blockIdx.x*blockDim.y + threadIdx.y,
//   z = blockIdx.y, plane = blockIdx.z.  Zero per-thread divmod.
template<int Di, int Hi, int Wi, int Do, int Ho, int Wo>
__global__ void downsample_both(const float* __restrict__ def,
                                const float* __restrict__ img,
                                float* __restrict__ odef,
                                float* __restrict__ oimg,
                                float rD, float rH, float rW)
{
    constexpr int OVOL = Do * Ho * Wo;
    constexpr int IVOL = Di * Hi * Wi;

    int x = threadIdx.x;
    int y = blockIdx.x * blockDim.y + threadIdx.y;
    int z = blockIdx.y;
    int p = blockIdx.z;            // 0..7

    const float* in; float* outp;
    if (p < 6) { in = def + p * IVOL;       outp = odef + p * OVOL; }
    else       { in = img + (p - 6) * IVOL; outp = oimg + (p - 6) * OVOL; }

    float cz = (float)z * rD;
    float cy = (float)y * rH;
    float cx = (float)x * rW;
    int z0 = min((int)floorf(cz), Di - 1);
    int y0 = min((int)floorf(cy), Hi - 1);
    int x0 = min((int)floorf(cx), Wi - 1);
    float wz = cz - (float)z0;
    float wy = cy - (float)y0;
    float wx = cx - (float)x0;
    int z1 = min(z0 + 1, Di - 1);
    int y1 = min(y0 + 1, Hi - 1);
    int x1 = min(x0 + 1, Wi - 1);

    const float* pz0 = in + z0 * (Hi * Wi);
    const float* pz1 = in + z1 * (Hi * Wi);
    int oy0 = y0 * Wi, oy1 = y1 * Wi;

    float v000 = __ldg(pz0 + oy0 + x0), v001 = __ldg(pz0 + oy0 + x1);
    float v010 = __ldg(pz0 + oy1 + x0), v011 = __ldg(pz0 + oy1 + x1);
    float v100 = __ldg(pz1 + oy0 + x0), v101 = __ldg(pz1 + oy0 + x1);
    float v110 = __ldg(pz1 + oy1 + x0), v111 = __ldg(pz1 + oy1 + x1);

    float a00 = v000 * (1.f - wx) + v001 * wx;
    float a01 = v010 * (1.f - wx) + v011 * wx;
    float a10 = v100 * (1.f - wx) + v101 * wx;
    float a11 = v110 * (1.f - wx) + v111 * wx;
    float b0 = a00 * (1.f - wy) + a01 * wy;
    float b1 = a10 * (1.f - wy) + a11 * wy;
    outp[z * (Ho * Wo) + y * Wo + x] = b0 * (1.f - wz) + b1 * wz;
}

// ---------------------------------------------------------------------------
// torch.gradient of one field at 4 consecutive W positions.
template<int D, int H, int W>
__device__ __forceinline__ void field_grads(const float* __restrict__ f,
                                            int d, int h, int w,
                                            float4& gD, float4& gH, float4& gW_)
{
    constexpr int sH = W;
    constexpr int sD = H * W;
    const float* base = f + d * sD + h * sH + w;

    float4 c = __ldg(reinterpret_cast<const float4*>(base));

    float xl = (w > 0)     ? __ldg(base - 1) : 0.f;
    float xr = (w + 4 < W) ? __ldg(base + 4) : 0.f;
    gW_.x = (w == 0)     ? (c.y - c.x) : 0.5f * (c.y - xl);
    gW_.y = 0.5f * (c.z - c.x);
    gW_.z = 0.5f * (c.w - c.y);
    gW_.w = (w + 4 == W) ? (c.w - c.z) : 0.5f * (xr - c.z);

    float4 hm = __ldg(reinterpret_cast<const float4*>(base - (h > 0     ? sH : 0)));
    float4 hp = __ldg(reinterpret_cast<const float4*>(base + (h < H - 1 ? sH : 0)));
    float sh = (h == 0 || h == H - 1) ? 1.0f : 0.5f;
    gH.x = sh * (hp.x - hm.x); gH.y = sh * (hp.y - hm.y);
    gH.z = sh * (hp.z - hm.z); gH.w = sh * (hp.w - hm.w);

    float4 dm = __ldg(reinterpret_cast<const float4*>(base - (d > 0     ? sD : 0)));
    float4 dp = __ldg(reinterpret_cast<const float4*>(base + (d < D - 1 ? sD : 0)));
    float sd = (d == 0 || d == D - 1) ? 1.0f : 0.5f;
    gD.x = sd * (dp.x - dm.x); gD.y = sd * (dp.y - dm.y);
    gD.z = sd * (dp.z - dm.z); gD.w = sd * (dp.w - dm.w);
}

__device__ __forceinline__ float4 f4add(float4 a, float4 b) {
    return make_float4(a.x + b.x, a.y + b.y, a.z + b.z, a.w + b.w);
}

// ---------------------------------------------------------------------------
// Flat energy kernel (warp-contiguous loads), register-light field-by-field
// strain accumulation. Proven fastest variant (R7).
template<int D, int H, int W>
__global__ void __launch_bounds__(256)
energy_flat(const float* __restrict__ def, const float* __restrict__ img,
            int scale_idx)
{
    constexpr int Wq = W >> 2;
    constexpr int TOTAL = 2 * D * H * Wq;
    constexpr int VOL = D * H * W;
    int i = blockIdx.x * 256 + threadIdx.x;

    float local = 0.f;
    if (i < TOTAL) {
        int xq = i % Wq; int t = i / Wq;
        int h = t % H;   t /= H;
        int d = t % D;
        int n = t / D;
        int w = xq << 2;

        const float* base = def + n * 3 * VOL;

        float4 Exx, Eyy, Ezz, Sxy, Sxz, Syz;   // Sab = 2*Eab
        {
            float4 gD, gH, gW;
            field_grads<D, H, W>(base, d, h, w, gD, gH, gW);   // u
            Exx = gD; Sxy = gH; Sxz = gW;
        }
        {
            float4 gD, gH, gW;
            field_grads<D, H, W>(base + VOL, d, h, w, gD, gH, gW);   // v
            Eyy = gH; Sxy = f4add(Sxy, gD); Syz = gW;
        }
        {
            float4 gD, gH, gW;
            field_grads<D, H, W>(base + 2 * VOL, d, h, w, gD, gH, gW);   // w
            Ezz = gW; Sxz = f4add(Sxz, gD); Syz = f4add(Syz, gH);
        }
        float4 g2;
        {
            float4 gD, gH, gW;
            field_grads<D, H, W>(img + n * VOL, d, h, w, gD, gH, gW);
            g2.x = gD.x * gD.x + gH.x * gH.x + gW.x * gW.x;
            g2.y = gD.y * gD.y + gH.y * gH.y + gW.y * gW.y;
            g2.z = gD.z * gD.z + gH.z * gH.z + gW.z * gW.z;
            g2.w = gD.w * gD.w + gH.w * gH.w + gW.w * gW.w;
        }

        const float* exx = reinterpret_cast<const float*>(&Exx);
        const float* eyy = reinterpret_cast<const float*>(&Eyy);
        const float* ezz = reinterpret_cast<const float*>(&Ezz);
        const float* sxy = reinterpret_cast<const float*>(&Sxy);
        const float* sxz = reinterpret_cast<const float*>(&Sxz);
        const float* syz = reinterpret_cast<const float*>(&Syz);
        const float* gg  = reinterpret_cast<const float*>(&g2);

        #pragma unroll
        for (int j = 0; j < 4; j++) {
            float exy = 0.5f * sxy[j];
            float exz = 0.5f * sxz[j];
            float eyz = 0.5f * syz[j];
            float tr = exx[j] + eyy[j] + ezz[j];
            float g = sqrtf(gg[j]);
            float lam = 1.0f + 0.5f * g;
            float mu  = 1.0f + 0.5f * g;
            float e = 0.5f * lam * tr * tr
                    + mu * (exx[j] * exx[j] + eyy[j] * eyy[j] + ezz[j] * ezz[j]
                            + 2.0f * (exy * exy + exz * exz + eyz * eyz));
            local += (1.0f + 0.1f * g) * e;
        }
    }

    #pragma unroll
    for (int o = 16; o > 0; o >>= 1)
        local += __shfl_down_sync(0xffffffffu, local, o);

    __shared__ float ws[8];
    int lane = threadIdx.x & 31;
    int wid  = threadIdx.x >> 5;
    if (lane == 0) ws[wid] = local;
    __syncthreads();
    if (wid == 0) {
        float s = (lane < 8) ? ws[lane] : 0.f;
        #pragma unroll
        for (int o = 4; o > 0; o >>= 1)
            s += __shfl_down_sync(0xffffffffu, s, o);
        if (lane == 0)
            atomicAdd(&g_acc[scale_idx], (double)s);
    }
}

// ---------------------------------------------------------------------------
__global__ void finalize_kernel(float* out) {
    double m0 = g_acc[0] / (2.0 * VOL0);
    double m1 = g_acc[1] / (2.0 * VOL1);
    double m2 = g_acc[2] / (2.0 * VOL2);
    out[0] = (float)(m0 + m1 + m2);
}

// ---------------------------------------------------------------------------
extern "C" void kernel_launch(void* const* d_in, const int* in_sizes, int n_in,
                              void* d_out, int out_size)
{
    const float* def = (const float*)d_in[0];
    const float* img = (const float*)d_in[1];
    float* out = (float*)d_out;

    float *p_def1, *p_img1, *p_def2, *p_img2;
    cudaGetSymbolAddress((void**)&p_def1, g_def1);
    cudaGetSymbolAddress((void**)&p_img1, g_img1);
    cudaGetSymbolAddress((void**)&p_def2, g_def2);
    cudaGetSymbolAddress((void**)&p_img2, g_img2);

    // Side stream + events, created once on the (uncaptured) correctness call.
    static cudaStream_t s_side = nullptr;
    static cudaEvent_t  s_fork = nullptr, s_join = nullptr;
    if (s_side == nullptr) {
        cudaStreamCreateWithFlags(&s_side, cudaStreamNonBlocking);
        cudaEventCreateWithFlags(&s_fork, cudaEventDisableTiming);
        cudaEventCreateWithFlags(&s_join, cudaEventDisableTiming);
    }

    init_acc_kernel<<<1, 32>>>();

    // Fork: scales 1 & 2 on the side stream, concurrent with scale 0.
    cudaEventRecord(s_fork, 0);
    cudaStreamWaitEvent(s_side, s_fork, 0);

    // ---- side stream: scale 1 then scale 2 ----
    {
        float rD = (float)((double)(D0 - 1) / (double)(D1 - 1));
        float rH = (float)((double)(H0 - 1) / (double)(H1 - 1));
        float rW = (float)((double)(W0 - 1) / (double)(W1 - 1));
        dim3 blk(W1, 3);
        dim3 grd(H1 / 3, D1, 8);
        downsample_both<D0, H0, W0, D1, H1, W1>
            <<<grd, blk, 0, s_side>>>(def, img, p_def1, p_img1, rD, rH, rW);

        constexpr int T1 = 2 * D1 * H1 * (W1 / 4);
        energy_flat<D1, H1, W1><<<(T1 + 255) / 256, 256, 0, s_side>>>(p_def1, p_img1, 1);
    }
    {
        float rD = (float)((double)(D0 - 1) / (double)(D2 - 1));
        float rH = (float)((double)(H0 - 1) / (double)(H2 - 1));
        float rW = (float)((double)(W0 - 1) / (double)(W2 - 1));
        dim3 blk(W2, 6);
        dim3 grd(H2 / 6, D2, 8);
        downsample_both<D0, H0, W0, D2, H2, W2>
            <<<grd, blk, 0, s_side>>>(def, img, p_def2, p_img2, rD, rH, rW);

        constexpr int T2 = 2 * D2 * H2 * (W2 / 4);
        energy_flat<D2, H2, W2><<<(T2 + 255) / 256, 256, 0, s_side>>>(p_def2, p_img2, 2);
    }

    // ---- main stream: scale 0 ----
    {
        constexpr int T0 = 2 * D0 * H0 * (W0 / 4);
        energy_flat<D0, H0, W0><<<(T0 + 255) / 256, 256>>>(def, img, 0);
    }

    // Join, then finalize.
    cudaEventRecord(s_join, s_side);
    cudaStreamWaitEvent(0, s_join, 0);
    finalize_kernel<<<1, 1>>>(out);
}